// round 4
// baseline (speedup 1.0000x reference)
#include <cuda_runtime.h>
#include <cuda_bf16.h>
#include <math.h>

#define F 128
#define NMAX 50000
#define EMAX 800000
#define CAP 64      // bucket capacity per destination row (P(deg>=64) ~ 0)

// static scratch (no allocations allowed)
__device__ float2 g_slots[(size_t)NMAX * CAP];     // (src_bits, w) buckets, 25.6 MB
__device__ int    g_cnt[NMAX];
__device__ float4 g_over[EMAX];                    // overflow edges (src,dst,w,-)
__device__ int    g_overcnt;

// ---------------------------------------------------------------------------
// Kernel 1: zero bucket counters
// ---------------------------------------------------------------------------
__global__ void zero_cnt_kernel(int Nn) {
    int i = blockIdx.x * blockDim.x + threadIdx.x;
    if (i < Nn) g_cnt[i] = 0;
    if (i == 0) g_overcnt = 0;
}

// ---------------------------------------------------------------------------
// Kernel 2: bucket fill. One thread per edge. Overflow -> side list.
// ---------------------------------------------------------------------------
__global__ void fill_kernel(const float* __restrict__ edge_w,
                            const int* __restrict__ edge_src,
                            const int* __restrict__ edge_dst,
                            int E) {
    int e = blockIdx.x * blockDim.x + threadIdx.x;
    if (e >= E) return;
    int d = edge_dst[e];
    int s = edge_src[e];
    float w = edge_w[e];
    int pos = atomicAdd(&g_cnt[d], 1);
    if (pos < CAP) {
        g_slots[(size_t)d * CAP + pos] = make_float2(__int_as_float(s), w);
    } else {
        int o = atomicAdd(&g_overcnt, 1);
        if (o < EMAX)
            g_over[o] = make_float4(__int_as_float(s), __int_as_float(d), w, 0.f);
    }
}

// ---------------------------------------------------------------------------
// Kernel 3: FUSED gather + GEMM + residual.
//   Per warp: gather 8 rows of S = (1-a)*A@x + a*h0 into a private smem
//   slice, then mini-GEMM (8x128) @ W' with FFMA2 column pairs, + x, store.
//   W' = theta*W + (1-theta)*I lives in smem (built once per block).
//   Gather-phase warps stall on L2 while compute-phase warps use the FMA
//   pipe -> memory/compute overlap inside one kernel.
// ---------------------------------------------------------------------------
#define PACK2(dst, lo, hi) \
    asm("mov.b64 %0, {%1, %2};" : "=l"(dst) : "f"(lo), "f"(hi))
#define UNPACK2(lo, hi, src) \
    asm("mov.b64 {%0, %1}, %2;" : "=f"(lo), "=f"(hi) : "l"(src))
#define FMA2(acc, a, b) \
    asm("fma.rn.f32x2 %0, %1, %2, %0;" : "+l"(acc) : "l"(a), "l"(b))

__global__ void __launch_bounds__(256, 2)
fused_kernel(const float* __restrict__ x,
             const float* __restrict__ h0,
             const float* __restrict__ weight,
             const float* __restrict__ lamda_p,
             const float* __restrict__ alpha_p,
             const int* __restrict__ l_p,
             float* __restrict__ out,
             int Nn) {
    extern __shared__ float sh[];
    float* Wp = sh;                        // 128x128 = 64 KB
    float* stw = sh + F * F + (threadIdx.x >> 5) * (8 * F);  // warp's S slice

    int tid = threadIdx.x;
    int lane = tid & 31;                   // lane -> cols 4*lane .. 4*lane+3
    int wrp = tid >> 5;                    // warp -> 8 rows of each tile

    float theta = logf(lamda_p[0] / (float)l_p[0] + 1.0f);
    float omt = 1.0f - theta;
    float alpha = alpha_p[0];
    float oma = 1.0f - alpha;

    // W'[k][j] = theta*W[k][j] + (k==j ? 1-theta : 0)
    for (int i = tid; i < F * F; i += 256) {
        int k = i >> 7;
        int j = i & 127;
        float v = theta * weight[i];
        if (k == j) v += omt;
        Wp[i] = v;
    }
    __syncthreads();

    int ntiles = (Nn + 63) / 64;           // 64 rows per block-tile
    for (int t = blockIdx.x; t < ntiles; t += gridDim.x) {
        int rowbase = t * 64 + wrp * 8;    // this warp's 8 rows

        // ---- gather phase: build 8 S rows in smem ----
        #pragma unroll 1
        for (int r = 0; r < 8; r++) {
            int row = rowbase + r;
            if (row >= Nn) {               // pad
                *(float4*)&stw[r * F + 4 * lane] = make_float4(0.f, 0.f, 0.f, 0.f);
                continue;
            }
            int cnt_raw = g_cnt[row];
            int cnt = min(cnt_raw, CAP);

            float4 acc = make_float4(0.f, 0.f, 0.f, 0.f);
            const float2* slotp = g_slots + (size_t)row * CAP;

            for (int base = 0; base < cnt; base += 32) {
                int m = min(32, cnt - base);
                float2 myslot = (lane < m) ? slotp[base + lane]
                                           : make_float2(0.f, 0.f);
                int ms = __float_as_int(myslot.x);
                #pragma unroll 4
                for (int e = 0; e < m; e++) {
                    int   s  = __shfl_sync(0xffffffffu, ms, e);
                    float wt = __shfl_sync(0xffffffffu, myslot.y, e);
                    float4 v = ((const float4*)(x + (size_t)s * F))[lane];
                    acc.x += wt * v.x;
                    acc.y += wt * v.y;
                    acc.z += wt * v.z;
                    acc.w += wt * v.w;
                }
            }

            // overflow drain (normally dead code; correct for any degree)
            if (cnt_raw > CAP) {
                int oc = g_overcnt;
                if (oc > EMAX) oc = EMAX;
                for (int o = 0; o < oc; o++) {
                    float4 ov = g_over[o];            // broadcast load
                    if (__float_as_int(ov.y) == row) {
                        int s = __float_as_int(ov.x);
                        float wt = ov.z;
                        float4 v = ((const float4*)(x + (size_t)s * F))[lane];
                        acc.x += wt * v.x;
                        acc.y += wt * v.y;
                        acc.z += wt * v.z;
                        acc.w += wt * v.w;
                    }
                }
            }

            float4 hv = ((const float4*)(h0 + (size_t)row * F))[lane];
            float4 S;
            S.x = oma * acc.x + alpha * hv.x;
            S.y = oma * acc.y + alpha * hv.y;
            S.z = oma * acc.z + alpha * hv.z;
            S.w = oma * acc.w + alpha * hv.w;
            *(float4*)&stw[r * F + 4 * lane] = S;
        }
        __syncwarp();

        // ---- compute phase: (8 x 128) @ W' with FFMA2 column pairs ----
        unsigned long long acc2[8][2];
        #pragma unroll
        for (int r = 0; r < 8; r++) { acc2[r][0] = 0ull; acc2[r][1] = 0ull; }

        for (int k = 0; k < F; k += 2) {
            float4 w0 = *(const float4*)&Wp[k * F + 4 * lane];
            float4 w1 = *(const float4*)&Wp[(k + 1) * F + 4 * lane];
            unsigned long long wp00, wp01, wp10, wp11;
            PACK2(wp00, w0.x, w0.y); PACK2(wp01, w0.z, w0.w);
            PACK2(wp10, w1.x, w1.y); PACK2(wp11, w1.z, w1.w);
            #pragma unroll
            for (int r = 0; r < 8; r++) {
                float2 s2 = *(const float2*)&stw[r * F + k];   // broadcast
                unsigned long long sp0, sp1;
                PACK2(sp0, s2.x, s2.x);
                PACK2(sp1, s2.y, s2.y);
                FMA2(acc2[r][0], sp0, wp00);
                FMA2(acc2[r][1], sp0, wp01);
                FMA2(acc2[r][0], sp1, wp10);
                FMA2(acc2[r][1], sp1, wp11);
            }
        }

        #pragma unroll
        for (int r = 0; r < 8; r++) {
            int row = rowbase + r;
            if (row < Nn) {
                float a0, a1, a2, a3;
                UNPACK2(a0, a1, acc2[r][0]);
                UNPACK2(a2, a3, acc2[r][1]);
                size_t base = (size_t)row * F + 4 * lane;
                float4 xv = *(const float4*)(x + base);
                float4 o = make_float4(a0 + xv.x, a1 + xv.y,
                                       a2 + xv.z, a3 + xv.w);
                *(float4*)(out + base) = o;
            }
        }
        __syncwarp();   // protect stw before next tile's gather overwrites it
    }
}

// ---------------------------------------------------------------------------
extern "C" void kernel_launch(void* const* d_in, const int* in_sizes, int n_in,
                              void* d_out, int out_size) {
    const float* x      = (const float*)d_in[0];
    const float* h0     = (const float*)d_in[1];
    const float* ew     = (const float*)d_in[2];
    const float* weight = (const float*)d_in[3];
    const float* lamda  = (const float*)d_in[4];
    const float* alpha  = (const float*)d_in[5];
    const int*   esrc   = (const int*)d_in[6];
    const int*   edst   = (const int*)d_in[7];
    const int*   lp     = (const int*)d_in[8];

    int Nn = in_sizes[0] / F;
    int E  = in_sizes[2];
    float* out = (float*)d_out;

    // 1) zero counters
    zero_cnt_kernel<<<(Nn + 255) / 256, 256>>>(Nn);

    // 2) bucket fill
    fill_kernel<<<(E + 255) / 256, 256>>>(ew, esrc, edst, E);

    // 3) fused gather + GEMM + residual
    int smem_bytes = (F * F + 8 * 8 * F) * (int)sizeof(float);   // 98304
    cudaFuncSetAttribute(fused_kernel,
                         cudaFuncAttributeMaxDynamicSharedMemorySize, smem_bytes);
    fused_kernel<<<296, 256, smem_bytes>>>(x, h0, weight, lamda, alpha, lp,
                                           out, Nn);
}